// round 5
// baseline (speedup 1.0000x reference)
#include <cuda_runtime.h>
#include <cuda_bf16.h>
#include <math.h>

#define NB 16  // batch

// ---------------- packed f32x2 helpers (sm_100+ PTX) --------------------------
#define FMA2(d, a, b, c) \
    asm("fma.rn.f32x2 %0, %1, %2, %3;" : "=l"(d) : "l"(a), "l"(b), "l"(c))
__device__ __forceinline__ unsigned long long pack2(float lo, float hi) {
    unsigned long long r;
    asm("mov.b64 %0, {%1, %2};" : "=l"(r) : "r"(__float_as_uint(lo)), "r"(__float_as_uint(hi)));
    return r;
}
__device__ __forceinline__ void unpack2(unsigned long long v, float& lo, float& hi) {
    unsigned int a, b;
    asm("mov.b64 {%0, %1}, %2;" : "=r"(a), "=r"(b) : "l"(v));
    lo = __uint_as_float(a); hi = __uint_as_float(b);
}

// ---------------- scratch (device globals; no allocation allowed) -------------
__device__ float g_v[NB*49*2048];        // transposed vision (B,49,2048)
__device__ float g_tv[NB*49*49];         // vision hidden pre/post BN
__device__ float g_vquery[NB*49*2048];
__device__ float g_vkeys[NB*49*2048];
__device__ float g_scores[(size_t)NB*2048*2048];  // 268 MB raw (scaled) logits
__device__ float g_ta[NB*64*64];
__device__ float g_aquery[NB*64*128];
__device__ float g_akeys[NB*64*128];
__device__ float g_scores_a[NB*128*128];
__device__ float g_mean[4*64];
__device__ float g_rstd[4*64];
__device__ float g_pmax[(size_t)NB*2048*32];  // per-(row, e-tile) partial max
__device__ float g_psum[(size_t)NB*2048*32];  // per-(row, e-tile) partial sumexp
__device__ float g_smax[NB*2048];        // per-row softmax max
__device__ float g_sinv[NB*2048];        // per-row 1/sum(exp)

// ---------------- transpose Vision (B,2048,49) -> g_v (B,49,2048) -------------
__global__ void k_transpose(const float* __restrict__ vis, float* __restrict__ out) {
    int b = blockIdx.x, dt = blockIdx.y;
    __shared__ float s[32*49];
    int d0 = dt * 32;
    const float* src = vis + ((size_t)b*2048 + d0)*49;
    for (int i = threadIdx.x; i < 32*49; i += blockDim.x) s[i] = src[i];
    __syncthreads();
    float* dst = out + (size_t)b*49*2048;
    for (int i = threadIdx.x; i < 49*32; i += blockDim.x) {
        int n = i >> 5, dd = i & 31;
        dst[n*2048 + d0 + dd] = s[dd*49 + n];
    }
}

// ---- out[bn][h] = bias[h] + sum_d x[bn][d] * W[h][d] -------------------------
template<int D, int H>
__global__ void k_rowgemm_AT(const float* __restrict__ x, const float* __restrict__ W,
                             const float* __restrict__ bias, float* __restrict__ out) {
    int bn = blockIdx.x;
    __shared__ float s[D];
    const float* row = x + (size_t)bn*D;
    for (int i = threadIdx.x; i < D; i += blockDim.x) s[i] = row[i];
    __syncthreads();
    for (int h = threadIdx.x; h < H; h += blockDim.x) {
        const float* w = W + (size_t)h*D;
        float acc = 0.f;
        #pragma unroll 8
        for (int d = 0; d < D; d++) acc += s[d]*w[d];
        out[(size_t)bn*H + h] = acc + bias[h];
    }
}

// ---- out[bn][d] = bias[d] + sum_h x[bn][h] * W[d][h] -------------------------
template<int H, int D>
__global__ void k_rowgemm_B(const float* __restrict__ x, const float* __restrict__ W,
                            const float* __restrict__ bias, float* __restrict__ out) {
    int bn = blockIdx.x;
    __shared__ float s[H];
    const float* row = x + (size_t)bn*H;
    for (int i = threadIdx.x; i < H; i += blockDim.x) s[i] = row[i];
    __syncthreads();
    for (int d = threadIdx.x; d < D; d += blockDim.x) {
        const float* w = W + (size_t)d*H;
        float acc = bias[d];
        #pragma unroll
        for (int h = 0; h < H; h++) acc += s[h]*w[h];
        out[(size_t)bn*D + d] = acc;
    }
}

// ---- out[b][o][d] = bias[o] + sum_n W[o][n] * x[b][n][d]  (1x1 conv) ---------
template<int N, int D>
__global__ void k_conv(const float* __restrict__ x, const float* __restrict__ W,
                       const float* __restrict__ bias, float* __restrict__ out, int O) {
    int b = blockIdx.y, o = blockIdx.x;
    __shared__ float w[N];
    for (int i = threadIdx.x; i < N; i += blockDim.x) w[i] = W[o*N + i];
    __syncthreads();
    const float* xb = x + (size_t)b*N*D;
    float bo = bias[o];
    for (int d = threadIdx.x; d < D; d += blockDim.x) {
        float acc = bo;
        #pragma unroll
        for (int n = 0; n < N; n++) acc += w[n]*xb[n*D + d];
        out[((size_t)b*O + o)*D + d] = acc;
    }
}

// ---- BatchNorm stats over (b, l) per channel c of x[B][C][L] ------------------
__global__ void k_bnstats(const float* __restrict__ x, int C, int L,
                          float* __restrict__ mean, float* __restrict__ rstd) {
    int c = blockIdx.x;
    float s = 0.f, s2 = 0.f;
    int nTot = NB * L;
    for (int i = threadIdx.x; i < nTot; i += blockDim.x) {
        int b = i / L, l = i - b*L;
        float v = x[((size_t)b*C + c)*L + l];
        s += v; s2 += v*v;
    }
    __shared__ float rs[256], rs2[256];
    rs[threadIdx.x] = s; rs2[threadIdx.x] = s2;
    __syncthreads();
    for (int off = 128; off > 0; off >>= 1) {
        if ((int)threadIdx.x < off) { rs[threadIdx.x] += rs[threadIdx.x+off];
                                      rs2[threadIdx.x] += rs2[threadIdx.x+off]; }
        __syncthreads();
    }
    if (threadIdx.x == 0) {
        float m = rs[0] / nTot;
        float var = rs2[0] / nTot - m*m;
        mean[c] = m;
        rstd[c] = rsqrtf(var + 1e-5f);
    }
}

// ---- apply BN + ReLU in place -------------------------------------------------
__global__ void k_bnapply(float* __restrict__ x, int C, int L,
                          const float* __restrict__ mean, const float* __restrict__ rstd,
                          const float* __restrict__ g, const float* __restrict__ bet) {
    size_t idx = (size_t)blockIdx.x*blockDim.x + threadIdx.x;
    size_t tot = (size_t)NB*C*L;
    if (idx >= tot) return;
    int c = (int)((idx / (size_t)L) % (size_t)C);
    float v = (x[idx] - mean[c]) * rstd[c] * g[c] + bet[c];
    x[idx] = fmaxf(v, 0.f);
}

// ---- audio scores: logits + softmax fused (row = 128 wide) -------------------
__global__ void k_scores_a(const float* __restrict__ keys, const float* __restrict__ qry,
                           float* __restrict__ sc) {
    int b = blockIdx.y, d = blockIdx.x;
    int e = threadIdx.x;                      // 128 threads
    __shared__ float kcol[64];
    if (e < 64) kcol[e] = keys[((size_t)b*64 + e)*128 + d];
    __syncthreads();
    float acc = 0.f;
    const float* qb = qry + (size_t)b*64*128;
    #pragma unroll
    for (int n = 0; n < 64; n++) acc += kcol[n]*qb[n*128 + e];
    acc *= 0.08838834764831845f;              // 1/sqrt(128)
    __shared__ float red[128];
    red[e] = acc; __syncthreads();
    for (int off = 64; off > 0; off >>= 1) {
        if (e < off) red[e] = fmaxf(red[e], red[e+off]);
        __syncthreads();
    }
    float mx = red[0]; __syncthreads();
    float ex = __expf(acc - mx);
    red[e] = ex; __syncthreads();
    for (int off = 64; off > 0; off >>= 1) {
        if (e < off) red[e] += red[e+off];
        __syncthreads();
    }
    sc[((size_t)b*128 + d)*128 + e] = ex / red[0];
}

// ---- a_out[b][n][e] = sum_d a[b][n][d] * sc[b][d][e] -------------------------
__global__ void k_aout(const float* __restrict__ a, const float* __restrict__ sc,
                       float* __restrict__ out) {
    int b = blockIdx.y, n = blockIdx.x;
    int e = threadIdx.x;                      // 128
    __shared__ float ar[128];
    ar[e] = a[((size_t)b*64 + n)*128 + e];
    __syncthreads();
    float acc = 0.f;
    const float* sb = sc + (size_t)b*128*128;
    #pragma unroll 8
    for (int d = 0; d < 128; d++) acc += ar[d]*sb[d*128 + e];
    out[((size_t)b*64 + n)*128 + e] = acc;
}

// ---- vision logits + per-tile softmax partials (f32x2 inner loop) ------------
__global__ void __launch_bounds__(256) k_logits_v(const float* __restrict__ keys,
                                                  const float* __restrict__ qry,
                                                  float* __restrict__ sc,
                                                  float* __restrict__ pmax,
                                                  float* __restrict__ psum) {
    int b = blockIdx.z;
    int d0 = blockIdx.y * 64, e0 = blockIdx.x * 64;
    __shared__ float As[49][64], Bs[49][64];
    const float* kb = keys + (size_t)b*49*2048;
    const float* qb = qry  + (size_t)b*49*2048;
    for (int i = threadIdx.x; i < 49*16; i += 256) {
        int n = i >> 4, c = (i & 15) << 2;
        *(float4*)&As[n][c] = *(const float4*)&kb[n*2048 + d0 + c];
        *(float4*)&Bs[n][c] = *(const float4*)&qb[n*2048 + e0 + c];
    }
    __syncthreads();
    int tx = threadIdx.x & 15, ty = threadIdx.x >> 4;
    unsigned long long acc2[4][2];
    #pragma unroll
    for (int i = 0; i < 4; i++) { acc2[i][0] = 0ULL; acc2[i][1] = 0ULL; }
    #pragma unroll 7
    for (int n = 0; n < 49; n++) {
        float4 a4 = *(const float4*)&As[n][ty*4];
        float4 b4 = *(const float4*)&Bs[n][tx*4];
        unsigned long long b01 = pack2(b4.x, b4.y);
        unsigned long long b23 = pack2(b4.z, b4.w);
        float av[4] = {a4.x, a4.y, a4.z, a4.w};
        #pragma unroll
        for (int i = 0; i < 4; i++) {
            unsigned long long ad = pack2(av[i], av[i]);
            FMA2(acc2[i][0], ad, b01, acc2[i][0]);
            FMA2(acc2[i][1], ad, b23, acc2[i][1]);
        }
    }
    const float scale = 0.02209708691207961f; // 1/sqrt(2048)
    float acc[4][4];
    #pragma unroll
    for (int i = 0; i < 4; i++) {
        unpack2(acc2[i][0], acc[i][0], acc[i][1]);
        unpack2(acc2[i][1], acc[i][2], acc[i][3]);
        #pragma unroll
        for (int j = 0; j < 4; j++) acc[i][j] *= scale;
    }
    float* scb = sc + ((size_t)b*2048 + d0)*2048 + e0;
    #pragma unroll
    for (int i = 0; i < 4; i++)
        *(float4*)&scb[(size_t)(ty*4+i)*2048 + tx*4] =
            make_float4(acc[i][0], acc[i][1], acc[i][2], acc[i][3]);
    // per-row (64-wide tile) partial softmax stats via 16-lane shuffles
    #pragma unroll
    for (int i = 0; i < 4; i++) {
        float rm = fmaxf(fmaxf(acc[i][0], acc[i][1]), fmaxf(acc[i][2], acc[i][3]));
        #pragma unroll
        for (int off = 8; off > 0; off >>= 1)
            rm = fmaxf(rm, __shfl_xor_sync(0xffffffffu, rm, off, 16));
        float rs = __expf(acc[i][0]-rm) + __expf(acc[i][1]-rm)
                 + __expf(acc[i][2]-rm) + __expf(acc[i][3]-rm);
        #pragma unroll
        for (int off = 8; off > 0; off >>= 1)
            rs += __shfl_xor_sync(0xffffffffu, rs, off, 16);
        if (tx == 0) {
            size_t idx = ((size_t)b*2048 + d0 + ty*4 + i)*32 + blockIdx.x;
            pmax[idx] = rm;
            psum[idx] = rs;
        }
    }
}

// ---- combine per-tile partials into row max and 1/sum ------------------------
__global__ void k_softfinal_v(const float* __restrict__ pmax, const float* __restrict__ psum,
                              float* __restrict__ smax, float* __restrict__ sinv) {
    size_t row = blockIdx.x;
    int t = threadIdx.x;                      // 32
    float m = pmax[row*32 + t];
    float s = psum[row*32 + t];
    float M = m;
    #pragma unroll
    for (int off = 16; off > 0; off >>= 1)
        M = fmaxf(M, __shfl_xor_sync(0xffffffffu, M, off));
    float S = s * __expf(m - M);
    #pragma unroll
    for (int off = 16; off > 0; off >>= 1)
        S += __shfl_xor_sync(0xffffffffu, S, off);
    if (t == 0) { smax[row] = M; sinv[row] = 1.f / S; }
}

// ---- v_out[b][n][e] = sum_d v[b][n][d] * softmax(sc)[b][d][e]  (f32x2) -------
// V tile stored transposed in smem: vst[dd][n], row stride 50, row n=49 zeroed.
__global__ void __launch_bounds__(128) k_vout(const float* __restrict__ v,
                                              const float* __restrict__ sc,
                                              const float* __restrict__ smax,
                                              const float* __restrict__ sinv,
                                              float* __restrict__ out) {
    int b = blockIdx.y;
    int e = blockIdx.x*128 + threadIdx.x;
    __shared__ float vst[64*50];
    __shared__ float sm[64], si[64];
    unsigned long long acc2[25];
    #pragma unroll
    for (int k = 0; k < 25; k++) acc2[k] = 0ULL;
    if (threadIdx.x < 64) vst[threadIdx.x*50 + 49] = 0.f;  // pad row stays zero
    const float* vb = v  + (size_t)b*49*2048;
    const float* sb = sc + (size_t)b*2048*2048;
    const float* mb = smax + (size_t)b*2048;
    const float* ib = sinv + (size_t)b*2048;
    for (int d0 = 0; d0 < 2048; d0 += 64) {
        __syncthreads();
        // transpose-fill: read float4 along d, scatter to vst[dd][n]
        for (int i = threadIdx.x; i < 49*16; i += 128) {
            int n = i >> 4, dd4 = (i & 15) << 2;
            float4 t = *(const float4*)&vb[n*2048 + d0 + dd4];
            vst[(dd4+0)*50 + n] = t.x;
            vst[(dd4+1)*50 + n] = t.y;
            vst[(dd4+2)*50 + n] = t.z;
            vst[(dd4+3)*50 + n] = t.w;
        }
        if (threadIdx.x < 64) {
            sm[threadIdx.x] = mb[d0 + threadIdx.x];
            si[threadIdx.x] = ib[d0 + threadIdx.x];
        }
        __syncthreads();
        #pragma unroll 4
        for (int dd = 0; dd < 64; dd++) {
            float p = __expf(sb[(size_t)(d0+dd)*2048 + e] - sm[dd]) * si[dd];
            unsigned long long pd = pack2(p, p);
            const unsigned long long* vr = (const unsigned long long*)&vst[dd*50];
            #pragma unroll
            for (int k = 0; k < 25; k++)
                FMA2(acc2[k], pd, vr[k], acc2[k]);
        }
    }
    #pragma unroll
    for (int k = 0; k < 25; k++) {
        float lo, hi;
        unpack2(acc2[k], lo, hi);
        int n = 2*k;
        out[((size_t)b*49 + n)*2048 + e] = lo;
        if (n + 1 < 49) out[((size_t)b*49 + n + 1)*2048 + e] = hi;
    }
}

// =============================================================================
extern "C" void kernel_launch(void* const* d_in, const int* in_sizes, int n_in,
                              void* d_out, int out_size) {
    const float* Vision = (const float*)d_in[0];
    const float* Audio  = (const float*)d_in[1];
    const float* aW1 = (const float*)d_in[2];
    const float* ab1 = (const float*)d_in[3];
    const float* a_g1 = (const float*)d_in[4];
    const float* a_b1 = (const float*)d_in[5];
    const float* aW2 = (const float*)d_in[6];
    const float* ab2 = (const float*)d_in[7];
    const float* vW1 = (const float*)d_in[8];
    const float* vb1 = (const float*)d_in[9];
    const float* v_g1 = (const float*)d_in[10];
    const float* v_b1 = (const float*)d_in[11];
    const float* vW2 = (const float*)d_in[12];
    const float* vb2 = (const float*)d_in[13];
    const float* kaW = (const float*)d_in[14];
    const float* kab = (const float*)d_in[15];
    const float* ka_g = (const float*)d_in[16];
    const float* ka_b = (const float*)d_in[17];
    const float* kvW = (const float*)d_in[18];
    const float* kvb = (const float*)d_in[19];
    const float* kv_g = (const float*)d_in[20];
    const float* kv_b = (const float*)d_in[21];
    // d_in[22] (embed_a), d_in[23] (embed_v) are dead in the reference output.

    float* out_v = (float*)d_out;                         // (16,49,2048)
    float* out_a = (float*)d_out + (size_t)NB*49*2048;    // (16,64,128)

    float *p_v, *p_tv, *p_vq, *p_vk, *p_sc, *p_ta, *p_aq, *p_ak, *p_sca,
          *p_mean, *p_rstd, *p_smax, *p_sinv, *p_pmax, *p_psum;
    cudaGetSymbolAddress((void**)&p_v,    g_v);
    cudaGetSymbolAddress((void**)&p_tv,   g_tv);
    cudaGetSymbolAddress((void**)&p_vq,   g_vquery);
    cudaGetSymbolAddress((void**)&p_vk,   g_vkeys);
    cudaGetSymbolAddress((void**)&p_sc,   g_scores);
    cudaGetSymbolAddress((void**)&p_ta,   g_ta);
    cudaGetSymbolAddress((void**)&p_aq,   g_aquery);
    cudaGetSymbolAddress((void**)&p_ak,   g_akeys);
    cudaGetSymbolAddress((void**)&p_sca,  g_scores_a);
    cudaGetSymbolAddress((void**)&p_mean, g_mean);
    cudaGetSymbolAddress((void**)&p_rstd, g_rstd);
    cudaGetSymbolAddress((void**)&p_smax, g_smax);
    cudaGetSymbolAddress((void**)&p_sinv, g_sinv);
    cudaGetSymbolAddress((void**)&p_pmax, g_pmax);
    cudaGetSymbolAddress((void**)&p_psum, g_psum);

    // ---------------- audio path (tiny) ----------------
    k_rowgemm_AT<128,64><<<NB*64, 128>>>(Audio, aW1, ab1, p_ta);
    k_bnstats<<<64, 256>>>(p_ta, 64, 64, p_mean + 0, p_rstd + 0);
    k_bnapply<<<(NB*64*64 + 255)/256, 256>>>(p_ta, 64, 64, p_mean + 0, p_rstd + 0, a_g1, a_b1);
    k_rowgemm_B<64,128><<<NB*64, 128>>>(p_ta, aW2, ab2, p_aq);
    k_conv<64,128><<<dim3(64, NB), 128>>>(Audio, kaW, kab, p_ak, 64);
    k_bnstats<<<64, 256>>>(p_ak, 64, 128, p_mean + 64, p_rstd + 64);
    k_bnapply<<<(NB*64*128 + 255)/256, 256>>>(p_ak, 64, 128, p_mean + 64, p_rstd + 64, ka_g, ka_b);
    k_scores_a<<<dim3(128, NB), 128>>>(p_ak, p_aq, p_sca);
    k_aout<<<dim3(64, NB), 128>>>(Audio, p_sca, out_a);

    // ---------------- vision path ----------------
    k_transpose<<<dim3(NB, 64), 256>>>(Vision, p_v);
    k_rowgemm_AT<2048,49><<<NB*49, 64>>>(p_v, vW1, vb1, p_tv);
    k_bnstats<<<49, 256>>>(p_tv, 49, 49, p_mean + 128, p_rstd + 128);
    k_bnapply<<<(NB*49*49 + 255)/256, 256>>>(p_tv, 49, 49, p_mean + 128, p_rstd + 128, v_g1, v_b1);
    k_rowgemm_B<49,2048><<<NB*49, 256>>>(p_tv, vW2, vb2, p_vq);
    k_conv<49,2048><<<dim3(49, NB), 256>>>(p_v, kvW, kvb, p_vk, 49);
    k_bnstats<<<49, 256>>>(p_vk, 49, 2048, p_mean + 192, p_rstd + 192);
    k_bnapply<<<(NB*49*2048 + 255)/256, 256>>>(p_vk, 49, 2048, p_mean + 192, p_rstd + 192, kv_g, kv_b);
    k_logits_v<<<dim3(32, 32, NB), 256>>>(p_vk, p_vq, p_sc, p_pmax, p_psum);
    k_softfinal_v<<<NB*2048, 32>>>(p_pmax, p_psum, p_smax, p_sinv);
    k_vout<<<dim3(16, NB), 128>>>(p_v, p_sc, p_smax, p_sinv, out_v);
}

// round 8
// speedup vs baseline: 2.0460x; 2.0460x over previous
#include <cuda_runtime.h>
#include <cuda_bf16.h>
#include <math.h>

#define NB 16  // batch

// ---------------- packed f32x2 helpers (sm_100+ PTX) --------------------------
#define FMA2(d, a, b, c) \
    asm("fma.rn.f32x2 %0, %1, %2, %3;" : "=l"(d) : "l"(a), "l"(b), "l"(c))
__device__ __forceinline__ unsigned long long pack2(float lo, float hi) {
    unsigned long long r;
    asm("mov.b64 %0, {%1, %2};" : "=l"(r) : "r"(__float_as_uint(lo)), "r"(__float_as_uint(hi)));
    return r;
}
__device__ __forceinline__ void unpack2(unsigned long long v, float& lo, float& hi) {
    unsigned int a, b;
    asm("mov.b64 {%0, %1}, %2;" : "=r"(a), "=r"(b) : "l"(v));
    lo = __uint_as_float(a); hi = __uint_as_float(b);
}

// ---------------- scratch (device globals; no allocation allowed) -------------
__device__ float g_v[NB*49*2048];        // transposed vision (B,49,2048)
__device__ float g_tv[NB*49*49];         // vision hidden (raw linear out)
__device__ float g_vquery[NB*49*2048];
__device__ float g_vkeys[NB*49*2048];    // raw conv out (BN folded at consumer)
__device__ float g_scores[(size_t)NB*2048*2048];  // 268 MB raw (scaled) logits
__device__ float g_ta[NB*64*64];
__device__ float g_aquery[NB*64*128];
__device__ float g_akeys[NB*64*128];
__device__ float g_scores_a[NB*128*128];
__device__ float g_bnscale[4*64];        // fused BN: x*scale + shift
__device__ float g_bnshift[4*64];
__device__ float g_pmax[(size_t)NB*2048*32];
__device__ float g_psum[(size_t)NB*2048*32];
__device__ float g_smax[NB*2048];
__device__ float g_sinv[NB*2048];
__device__ float g_aW2t[64*128];         // transposed aW2
__device__ float g_vW2t[49*2048];        // transposed vW2
__device__ float g_vpart[4*NB*49*2048];  // k_vout partials (25.7 MB)

// ---------------- transpose Vision (B,2048,49) -> g_v (B,49,2048) -------------
__global__ void k_transpose(const float* __restrict__ vis, float* __restrict__ out) {
    int b = blockIdx.x, dt = blockIdx.y;
    __shared__ float s[32*49];
    int d0 = dt * 32;
    const float* src = vis + ((size_t)b*2048 + d0)*49;
    for (int i = threadIdx.x; i < 32*49; i += blockDim.x) s[i] = src[i];
    __syncthreads();
    float* dst = out + (size_t)b*49*2048;
    for (int i = threadIdx.x; i < 49*32; i += blockDim.x) {
        int n = i >> 5, dd = i & 31;
        dst[n*2048 + d0 + dd] = s[dd*49 + n];
    }
}

// ---- transpose weight: in (D rows, H cols) -> out (H rows, D cols) -----------
__global__ void k_transW(const float* __restrict__ in, float* __restrict__ out,
                         int D, int H) {
    int idx = blockIdx.x*blockDim.x + threadIdx.x;
    if (idx >= D*H) return;
    int d = idx / H, h = idx - d*H;
    out[h*D + d] = in[idx];
}

// ---- out[bn][h] = bias[h] + sum_d x[bn][d]*W[h][d]  (warp per h, f4 lanes) ---
template<int D, int H>
__global__ void __launch_bounds__(256) k_rowgemm_AT(const float* __restrict__ x,
                                                    const float* __restrict__ W,
                                                    const float* __restrict__ bias,
                                                    float* __restrict__ out) {
    int bn = blockIdx.x;
    __shared__ float s[D];
    const float* row = x + (size_t)bn*D;
    for (int i = threadIdx.x*4; i < D; i += 1024)
        *(float4*)&s[i] = *(const float4*)&row[i];
    __syncthreads();
    int warp = threadIdx.x >> 5, lane = threadIdx.x & 31;
    for (int h = warp; h < H; h += 8) {
        const float* w = W + (size_t)h*D;
        float acc = 0.f;
        #pragma unroll
        for (int d = lane*4; d < D; d += 128) {
            float4 wv = *(const float4*)&w[d];
            float4 sv = *(const float4*)&s[d];
            acc += sv.x*wv.x + sv.y*wv.y + sv.z*wv.z + sv.w*wv.w;
        }
        #pragma unroll
        for (int off = 16; off > 0; off >>= 1)
            acc += __shfl_xor_sync(0xffffffffu, acc, off);
        if (lane == 0) out[(size_t)bn*H + h] = acc + bias[h];
    }
}

// ---- out[bn][d] = bias[d] + sum_h BN(x[bn][h]) * Wt[h][d]  (BN folded) -------
// Channel of BN = token index n = bn % NTOK (constant per row).
template<int H, int D, int NTOK>
__global__ void __launch_bounds__(256) k_rowgemm_Bt(const float* __restrict__ x,
                                                    const float* __restrict__ Wt,
                                                    const float* __restrict__ bias,
                                                    const float* __restrict__ scl,
                                                    const float* __restrict__ sft,
                                                    float* __restrict__ out) {
    int bn = blockIdx.x;
    int n = bn % NTOK;
    __shared__ float s[H];
    float sc = scl[n], sh = sft[n];
    const float* row = x + (size_t)bn*H;
    for (int i = threadIdx.x; i < H; i += 256)
        s[i] = fmaxf(fmaf(row[i], sc, sh), 0.f);
    __syncthreads();
    for (int d4 = threadIdx.x*4; d4 < D; d4 += 1024) {
        float4 acc = *(const float4*)&bias[d4];
        #pragma unroll
        for (int h = 0; h < H; h++) {
            float4 wv = *(const float4*)&Wt[(size_t)h*D + d4];
            float sv = s[h];
            acc.x = fmaf(sv, wv.x, acc.x);
            acc.y = fmaf(sv, wv.y, acc.y);
            acc.z = fmaf(sv, wv.z, acc.z);
            acc.w = fmaf(sv, wv.w, acc.w);
        }
        *(float4*)&out[(size_t)bn*D + d4] = acc;
    }
}

// ---- audio 1x1 conv: out[b][o][d] = bias[o] + sum_n W[o][n]*x[b][n][d] -------
template<int N, int D>
__global__ void k_conv(const float* __restrict__ x, const float* __restrict__ W,
                       const float* __restrict__ bias, float* __restrict__ out, int O) {
    int b = blockIdx.y, o = blockIdx.x;
    __shared__ float w[N];
    for (int i = threadIdx.x; i < N; i += blockDim.x) w[i] = W[o*N + i];
    __syncthreads();
    const float* xb = x + (size_t)b*N*D;
    float bo = bias[o];
    for (int d = threadIdx.x; d < D; d += blockDim.x) {
        float acc = bo;
        #pragma unroll
        for (int n = 0; n < N; n++) acc += w[n]*xb[n*D + d];
        out[((size_t)b*O + o)*D + d] = acc;
    }
}

// ---- vision 1x1 conv as smem mini-GEMM (f32x2, 49 accumulators) --------------
// out[b][o][d] = bias[o] + sum_n W[o][n]*x[b][n][d], o,n in [0,49), d 128-tile.
__global__ void __launch_bounds__(128) k_convv(const float* __restrict__ x,
                                               const float* __restrict__ W,
                                               const float* __restrict__ bias,
                                               float* __restrict__ out) {
    int b = blockIdx.y, d0 = blockIdx.x*128;
    __shared__ float xs[49*128];
    __shared__ float wst[49*50];   // wst[n][o], o padded to 50 (o=49 -> 0)
    __shared__ float bs[50];
    const float* xb = x + (size_t)b*49*2048;
    for (int i = threadIdx.x; i < 49*32; i += 128) {
        int n = i >> 5, dd4 = (i & 31) << 2;
        *(float4*)&xs[n*128 + dd4] = *(const float4*)&xb[n*2048 + d0 + dd4];
    }
    for (int i = threadIdx.x; i < 49*50; i += 128) {
        int n = i / 50, o = i - n*50;
        wst[i] = (o < 49) ? W[o*49 + n] : 0.f;
    }
    if (threadIdx.x < 50) bs[threadIdx.x] = (threadIdx.x < 49) ? bias[threadIdx.x] : 0.f;
    __syncthreads();
    int dd = threadIdx.x;
    unsigned long long acc2[25];
    #pragma unroll
    for (int k = 0; k < 25; k++) acc2[k] = 0ULL;
    #pragma unroll 7
    for (int n = 0; n < 49; n++) {
        float xv = xs[n*128 + dd];
        unsigned long long xd = pack2(xv, xv);
        const unsigned long long* wr = (const unsigned long long*)&wst[n*50];
        #pragma unroll
        for (int k = 0; k < 25; k++) FMA2(acc2[k], xd, wr[k], acc2[k]);
    }
    #pragma unroll
    for (int k = 0; k < 25; k++) {
        float lo, hi;
        unpack2(acc2[k], lo, hi);
        int o = 2*k;
        out[((size_t)b*49 + o)*2048 + d0 + dd] = lo + bs[o];
        if (o + 1 < 49)
            out[((size_t)b*49 + o + 1)*2048 + d0 + dd] = hi + bs[o+1];
    }
}

// ---- BN stats -> fused scale/shift: y = x*scale + shift ----------------------
__global__ void k_bnstats(const float* __restrict__ x, int C, int L,
                          const float* __restrict__ g, const float* __restrict__ bet,
                          float* __restrict__ scl, float* __restrict__ sft) {
    int c = blockIdx.x;
    float s = 0.f, s2 = 0.f;
    int nTot = NB * L;
    for (int i = threadIdx.x; i < nTot; i += blockDim.x) {
        int b = i / L, l = i - b*L;
        float v = x[((size_t)b*C + c)*L + l];
        s += v; s2 += v*v;
    }
    __shared__ float rs[256], rs2[256];
    rs[threadIdx.x] = s; rs2[threadIdx.x] = s2;
    __syncthreads();
    for (int off = 128; off > 0; off >>= 1) {
        if ((int)threadIdx.x < off) { rs[threadIdx.x] += rs[threadIdx.x+off];
                                      rs2[threadIdx.x] += rs2[threadIdx.x+off]; }
        __syncthreads();
    }
    if (threadIdx.x == 0) {
        float m = rs[0] / nTot;
        float var = rs2[0] / nTot - m*m;
        float rstd = rsqrtf(var + 1e-5f);
        float a = rstd * g[c];
        scl[c] = a;
        sft[c] = bet[c] - m*a;
    }
}

// ---- audio scores: BN(keys) + logits + softmax fused -------------------------
__global__ void k_scores_a(const float* __restrict__ keys, const float* __restrict__ qry,
                           const float* __restrict__ scl, const float* __restrict__ sft,
                           float* __restrict__ sc) {
    int b = blockIdx.y, d = blockIdx.x;
    int e = threadIdx.x;                      // 128 threads
    __shared__ float kcol[64];
    if (e < 64)
        kcol[e] = fmaxf(fmaf(keys[((size_t)b*64 + e)*128 + d], scl[e], sft[e]), 0.f);
    __syncthreads();
    float acc = 0.f;
    const float* qb = qry + (size_t)b*64*128;
    #pragma unroll
    for (int n = 0; n < 64; n++) acc += kcol[n]*qb[n*128 + e];
    acc *= 0.08838834764831845f;              // 1/sqrt(128)
    __shared__ float red[128];
    red[e] = acc; __syncthreads();
    for (int off = 64; off > 0; off >>= 1) {
        if (e < off) red[e] = fmaxf(red[e], red[e+off]);
        __syncthreads();
    }
    float mx = red[0]; __syncthreads();
    float ex = __expf(acc - mx);
    red[e] = ex; __syncthreads();
    for (int off = 64; off > 0; off >>= 1) {
        if (e < off) red[e] += red[e+off];
        __syncthreads();
    }
    sc[((size_t)b*128 + d)*128 + e] = ex / red[0];
}

// ---- a_out[b][n][e] = sum_d a[b][n][d] * sc[b][d][e] -------------------------
__global__ void k_aout(const float* __restrict__ a, const float* __restrict__ sc,
                       float* __restrict__ out) {
    int b = blockIdx.y, n = blockIdx.x;
    int e = threadIdx.x;                      // 128
    __shared__ float ar[128];
    ar[e] = a[((size_t)b*64 + n)*128 + e];
    __syncthreads();
    float acc = 0.f;
    const float* sb = sc + (size_t)b*128*128;
    #pragma unroll 8
    for (int d = 0; d < 128; d++) acc += ar[d]*sb[d*128 + e];
    out[((size_t)b*64 + n)*128 + e] = acc;
}

// ---- vision logits (BN folded on keys) + per-tile softmax partials -----------
__global__ void __launch_bounds__(256) k_logits_v(const float* __restrict__ keys,
                                                  const float* __restrict__ qry,
                                                  const float* __restrict__ scl,
                                                  const float* __restrict__ sft,
                                                  float* __restrict__ sc,
                                                  float* __restrict__ pmax,
                                                  float* __restrict__ psum) {
    int b = blockIdx.z;
    int d0 = blockIdx.y * 64, e0 = blockIdx.x * 64;
    __shared__ float As[49][64], Bs[49][64];
    const float* kb = keys + (size_t)b*49*2048;
    const float* qb = qry  + (size_t)b*49*2048;
    for (int i = threadIdx.x; i < 49*16; i += 256) {
        int n = i >> 4, c = (i & 15) << 2;
        float a = __ldg(&scl[n]), s = __ldg(&sft[n]);
        float4 t = *(const float4*)&kb[n*2048 + d0 + c];
        t.x = fmaxf(fmaf(t.x, a, s), 0.f);
        t.y = fmaxf(fmaf(t.y, a, s), 0.f);
        t.z = fmaxf(fmaf(t.z, a, s), 0.f);
        t.w = fmaxf(fmaf(t.w, a, s), 0.f);
        *(float4*)&As[n][c] = t;
        *(float4*)&Bs[n][c] = *(const float4*)&qb[n*2048 + e0 + c];
    }
    __syncthreads();
    int tx = threadIdx.x & 15, ty = threadIdx.x >> 4;
    unsigned long long acc2[4][2];
    #pragma unroll
    for (int i = 0; i < 4; i++) { acc2[i][0] = 0ULL; acc2[i][1] = 0ULL; }
    #pragma unroll 7
    for (int n = 0; n < 49; n++) {
        float4 a4 = *(const float4*)&As[n][ty*4];
        float4 b4 = *(const float4*)&Bs[n][tx*4];
        unsigned long long b01 = pack2(b4.x, b4.y);
        unsigned long long b23 = pack2(b4.z, b4.w);
        float av[4] = {a4.x, a4.y, a4.z, a4.w};
        #pragma unroll
        for (int i = 0; i < 4; i++) {
            unsigned long long ad = pack2(av[i], av[i]);
            FMA2(acc2[i][0], ad, b01, acc2[i][0]);
            FMA2(acc2[i][1], ad, b23, acc2[i][1]);
        }
    }
    const float scale = 0.02209708691207961f; // 1/sqrt(2048)
    float acc[4][4];
    #pragma unroll
    for (int i = 0; i < 4; i++) {
        unpack2(acc2[i][0], acc[i][0], acc[i][1]);
        unpack2(acc2[i][1], acc[i][2], acc[i][3]);
        #pragma unroll
        for (int j = 0; j < 4; j++) acc[i][j] *= scale;
    }
    float* scb = sc + ((size_t)b*2048 + d0)*2048 + e0;
    #pragma unroll
    for (int i = 0; i < 4; i++)
        *(float4*)&scb[(size_t)(ty*4+i)*2048 + tx*4] =
            make_float4(acc[i][0], acc[i][1], acc[i][2], acc[i][3]);
    #pragma unroll
    for (int i = 0; i < 4; i++) {
        float rm = fmaxf(fmaxf(acc[i][0], acc[i][1]), fmaxf(acc[i][2], acc[i][3]));
        #pragma unroll
        for (int off = 8; off > 0; off >>= 1)
            rm = fmaxf(rm, __shfl_xor_sync(0xffffffffu, rm, off, 16));
        float rs = __expf(acc[i][0]-rm) + __expf(acc[i][1]-rm)
                 + __expf(acc[i][2]-rm) + __expf(acc[i][3]-rm);
        #pragma unroll
        for (int off = 8; off > 0; off >>= 1)
            rs += __shfl_xor_sync(0xffffffffu, rs, off, 16);
        if (tx == 0) {
            size_t idx = ((size_t)b*2048 + d0 + ty*4 + i)*32 + blockIdx.x;
            pmax[idx] = rm;
            psum[idx] = rs;
        }
    }
}

// ---- combine per-tile partials into row max and 1/sum ------------------------
__global__ void k_softfinal_v(const float* __restrict__ pmax, const float* __restrict__ psum,
                              float* __restrict__ smax, float* __restrict__ sinv) {
    size_t row = blockIdx.x;
    int t = threadIdx.x;                      // 32
    float m = pmax[row*32 + t];
    float s = psum[row*32 + t];
    float M = m;
    #pragma unroll
    for (int off = 16; off > 0; off >>= 1)
        M = fmaxf(M, __shfl_xor_sync(0xffffffffu, M, off));
    float S = s * __expf(m - M);
    #pragma unroll
    for (int off = 16; off > 0; off >>= 1)
        S += __shfl_xor_sync(0xffffffffu, S, off);
    if (t == 0) { smax[row] = M; sinv[row] = 1.f / S; }
}

// ---- v_out partial over d-range: part[bz][b][n][e] ---------------------------
__global__ void __launch_bounds__(128) k_vout(const float* __restrict__ v,
                                              const float* __restrict__ sc,
                                              const float* __restrict__ smax,
                                              const float* __restrict__ sinv,
                                              float* __restrict__ part) {
    int b = blockIdx.y, dz = blockIdx.z;
    int e = blockIdx.x*128 + threadIdx.x;
    __shared__ float vst[64*50];
    __shared__ float sm[64], si[64];
    unsigned long long acc2[25];
    #pragma unroll
    for (int k = 0; k < 25; k++) acc2[k] = 0ULL;
    if (threadIdx.x < 64) vst[threadIdx.x*50 + 49] = 0.f;
    const float* vb = v  + (size_t)b*49*2048;
    const float* sb = sc + (size_t)b*2048*2048;
    const float* mb = smax + (size_t)b*2048;
    const float* ib = sinv + (size_t)b*2048;
    int dlo = dz*512, dhi = dlo + 512;
    for (int d0 = dlo; d0 < dhi; d0 += 64) {
        __syncthreads();
        for (int i = threadIdx.x; i < 49*16; i += 128) {
            int n = i >> 4, dd4 = (i & 15) << 2;
            float4 t = *(const float4*)&vb[n*2048 + d0 + dd4];
            vst[(dd4+0)*50 + n] = t.x;
            vst[(dd4+1)*50 + n] = t.y;
            vst[(dd4+2)*50 + n] = t.z;
            vst[(dd4+3)*50 + n] = t.w;
        }
        if (threadIdx.x < 64) {
            sm[threadIdx.x] = mb[d0 + threadIdx.x];
            si[threadIdx.x] = ib[d0 + threadIdx.x];
        }
        __syncthreads();
        #pragma unroll 4
        for (int dd = 0; dd < 64; dd++) {
            float p = __expf(sb[(size_t)(d0+dd)*2048 + e] - sm[dd]) * si[dd];
            unsigned long long pd = pack2(p, p);
            const unsigned long long* vr = (const unsigned long long*)&vst[dd*50];
            #pragma unroll
            for (int k = 0; k < 25; k++)
                FMA2(acc2[k], pd, vr[k], acc2[k]);
        }
    }
    float* pb = part + ((size_t)dz*NB + b)*49*2048;
    #pragma unroll
    for (int k = 0; k < 25; k++) {
        float lo, hi;
        unpack2(acc2[k], lo, hi);
        int n = 2*k;
        pb[(size_t)n*2048 + e] = lo;
        if (n + 1 < 49) pb[(size_t)(n+1)*2048 + e] = hi;
    }
}

// ---- combine 4 d-split partials ----------------------------------------------
__global__ void k_vcombine(const float* __restrict__ part, float* __restrict__ out) {
    size_t i = (size_t)blockIdx.x*256 + threadIdx.x;
    const size_t STRIDE = (size_t)NB*49*2048;
    out[i] = (part[i] + part[i + STRIDE]) + (part[i + 2*STRIDE] + part[i + 3*STRIDE]);
}

// =============================================================================
extern "C" void kernel_launch(void* const* d_in, const int* in_sizes, int n_in,
                              void* d_out, int out_size) {
    const float* Vision = (const float*)d_in[0];
    const float* Audio  = (const float*)d_in[1];
    const float* aW1 = (const float*)d_in[2];
    const float* ab1 = (const float*)d_in[3];
    const float* a_g1 = (const float*)d_in[4];
    const float* a_b1 = (const float*)d_in[5];
    const float* aW2 = (const float*)d_in[6];
    const float* ab2 = (const float*)d_in[7];
    const float* vW1 = (const float*)d_in[8];
    const float* vb1 = (const float*)d_in[9];
    const float* v_g1 = (const float*)d_in[10];
    const float* v_b1 = (const float*)d_in[11];
    const float* vW2 = (const float*)d_in[12];
    const float* vb2 = (const float*)d_in[13];
    const float* kaW = (const float*)d_in[14];
    const float* kab = (const float*)d_in[15];
    const float* ka_g = (const float*)d_in[16];
    const float* ka_b = (const float*)d_in[17];
    const float* kvW = (const float*)d_in[18];
    const float* kvb = (const float*)d_in[19];
    const float* kv_g = (const float*)d_in[20];
    const float* kv_b = (const float*)d_in[21];

    float* out_v = (float*)d_out;                         // (16,49,2048)
    float* out_a = (float*)d_out + (size_t)NB*49*2048;    // (16,64,128)

    float *p_v, *p_tv, *p_vq, *p_vk, *p_sc, *p_ta, *p_aq, *p_ak, *p_sca,
          *p_scl, *p_sft, *p_smax, *p_sinv, *p_pmax, *p_psum,
          *p_aW2t, *p_vW2t, *p_part;
    cudaGetSymbolAddress((void**)&p_v,    g_v);
    cudaGetSymbolAddress((void**)&p_tv,   g_tv);
    cudaGetSymbolAddress((void**)&p_vq,   g_vquery);
    cudaGetSymbolAddress((void**)&p_vk,   g_vkeys);
    cudaGetSymbolAddress((void**)&p_sc,   g_scores);
    cudaGetSymbolAddress((void**)&p_ta,   g_ta);
    cudaGetSymbolAddress((void**)&p_aq,   g_aquery);
    cudaGetSymbolAddress((void**)&p_ak,   g_akeys);
    cudaGetSymbolAddress((void**)&p_sca,  g_scores_a);
    cudaGetSymbolAddress((void**)&p_scl,  g_bnscale);
    cudaGetSymbolAddress((void**)&p_sft,  g_bnshift);
    cudaGetSymbolAddress((void**)&p_smax, g_smax);
    cudaGetSymbolAddress((void**)&p_sinv, g_sinv);
    cudaGetSymbolAddress((void**)&p_pmax, g_pmax);
    cudaGetSymbolAddress((void**)&p_psum, g_psum);
    cudaGetSymbolAddress((void**)&p_aW2t, g_aW2t);
    cudaGetSymbolAddress((void**)&p_vW2t, g_vW2t);
    cudaGetSymbolAddress((void**)&p_part, g_vpart);

    // weight transposes (independent; run first)
    k_transW<<<(128*64 + 255)/256, 256>>>(aW2, p_aW2t, 128, 64);
    k_transW<<<(2048*49 + 255)/256, 256>>>(vW2, p_vW2t, 2048, 49);

    // ---------------- audio path ----------------
    k_rowgemm_AT<128,64><<<NB*64, 256>>>(Audio, aW1, ab1, p_ta);
    k_bnstats<<<64, 256>>>(p_ta, 64, 64, a_g1, a_b1, p_scl + 0, p_sft + 0);
    k_rowgemm_Bt<64,128,64><<<NB*64, 256>>>(p_ta, p_aW2t, ab2, p_scl + 0, p_sft + 0, p_aq);
    k_conv<64,128><<<dim3(64, NB), 128>>>(Audio, kaW, kab, p_ak, 64);
    k_bnstats<<<64, 256>>>(p_ak, 64, 128, ka_g, ka_b, p_scl + 64, p_sft + 64);
    k_scores_a<<<dim3(128, NB), 128>>>(p_ak, p_aq, p_scl + 64, p_sft + 64, p_sca);
    k_aout<<<dim3(64, NB), 128>>>(Audio, p_sca, out_a);

    // ---------------- vision path ----------------
    k_transpose<<<dim3(NB, 64), 256>>>(Vision, p_v);
    k_rowgemm_AT<2048,49><<<NB*49, 256>>>(p_v, vW1, vb1, p_tv);
    k_bnstats<<<49, 256>>>(p_tv, 49, 49, v_g1, v_b1, p_scl + 128, p_sft + 128);
    k_rowgemm_Bt<49,2048,49><<<NB*49, 256>>>(p_tv, p_vW2t, vb2, p_scl + 128, p_sft + 128, p_vq);
    k_convv<<<dim3(16, NB), 128>>>(p_v, kvW, kvb, p_vk);
    k_bnstats<<<49, 256>>>(p_vk, 49, 2048, kv_g, kv_b, p_scl + 192, p_sft + 192);
    k_logits_v<<<dim3(32, 32, NB), 256>>>(p_vk, p_vq, p_scl + 192, p_sft + 192,
                                          p_sc, p_pmax, p_psum);
    k_softfinal_v<<<NB*2048, 32>>>(p_pmax, p_psum, p_smax, p_sinv);
    k_vout<<<dim3(16, NB, 4), 128>>>(p_v, p_sc, p_smax, p_sinv, p_part);
    k_vcombine<<<(NB*49*2048)/256, 256>>>(p_part, out_v);
}